// round 11
// baseline (speedup 1.0000x reference)
#include <cuda_runtime.h>
#include <cstdint>

#define C_DIM 1024
#define B_DIM 4
#define T_DIM 2048
#define H_DIM 16
#define HD    64
#define M_TOT (B_DIM * T_DIM)   // 8192
#define N_TOT (3 * C_DIM)       // 3072

// Q/K in [B,H,T,D]; V TRANSPOSED in [B,H,D,T]. All stored as tf32-rounded fp32 bits.
__device__ float g_q[(size_t)M_TOT * C_DIM];
__device__ float g_k[(size_t)M_TOT * C_DIM];
__device__ float g_v[(size_t)M_TOT * C_DIM];
// tf32-rounded copies of inputs
__device__ float g_xt[(size_t)M_TOT * C_DIM];
__device__ float g_wt[(size_t)N_TOT * C_DIM];

__device__ __forceinline__ uint32_t f2tf(float f) {
    uint32_t u;
    asm("cvt.rna.tf32.f32 %0, %1;" : "=r"(u) : "f"(f));
    return u;
}

__device__ __forceinline__ float ex2(float x) {
    float y;
    asm("ex2.approx.f32 %0, %1;" : "=f"(y) : "f"(x));
    return y;
}

__device__ __forceinline__ void mma_tf32(float c[4], const uint32_t a[4],
                                         uint32_t b0, uint32_t b1) {
    asm volatile(
        "mma.sync.aligned.m16n8k8.row.col.f32.tf32.tf32.f32 "
        "{%0,%1,%2,%3}, {%4,%5,%6,%7}, {%8,%9}, {%0,%1,%2,%3};"
        : "+f"(c[0]), "+f"(c[1]), "+f"(c[2]), "+f"(c[3])
        : "r"(a[0]), "r"(a[1]), "r"(a[2]), "r"(a[3]), "r"(b0), "r"(b1));
}

__device__ __forceinline__ void ldsm4(uint32_t& d0, uint32_t& d1,
                                      uint32_t& d2, uint32_t& d3,
                                      uint32_t addr) {
    asm volatile("ldmatrix.sync.aligned.m8n8.x4.shared.b16 {%0,%1,%2,%3}, [%4];"
                 : "=r"(d0), "=r"(d1), "=r"(d2), "=r"(d3) : "r"(addr));
}

__device__ __forceinline__ uint32_t smem_u32(const void* p) {
    uint32_t a;
    asm("{ .reg .u64 t; cvta.to.shared.u64 t, %1; cvt.u32.u64 %0, t; }"
        : "=r"(a) : "l"(p));
    return a;
}

__device__ __forceinline__ void cp16(uint32_t dst, const void* src) {
    asm volatile("cp.async.cg.shared.global [%0], [%1], 16;"
                 :: "r"(dst), "l"(src));
}
#define CP_COMMIT() asm volatile("cp.async.commit_group;" ::: "memory")
#define CP_WAIT0()  asm volatile("cp.async.wait_group 0;" ::: "memory")
#define CP_WAIT2()  asm volatile("cp.async.wait_group 2;" ::: "memory")

// ---------------------------------------------------------------------------
// Prepass: tf32-round (rna) x and W into scratch copies.
// ---------------------------------------------------------------------------
__global__ __launch_bounds__(256) void cvt_pre(
    const float* __restrict__ x, const float* __restrict__ W)
{
    const size_t nx = (size_t)M_TOT * C_DIM / 4;
    const size_t nw = (size_t)N_TOT * C_DIM / 4;
    size_t i = (size_t)blockIdx.x * blockDim.x + threadIdx.x;
    if (i < nx) {
        float4 v = ((const float4*)x)[i];
        uint4 u = { f2tf(v.x), f2tf(v.y), f2tf(v.z), f2tf(v.w) };
        ((uint4*)g_xt)[i] = u;
    } else if (i < nx + nw) {
        float4 v = ((const float4*)W)[i - nx];
        uint4 u = { f2tf(v.x), f2tf(v.y), f2tf(v.z), f2tf(v.w) };
        ((uint4*)g_wt)[i - nx] = u;
    }
}

// ---------------------------------------------------------------------------
// QKV GEMM: CTA tile 128x256, k16, 8 warps (2M x 4N), warp tile 64x64.
// 4-stage cp.async ring, ONE sync per k-tile, ldmatrix fragments.
// Q/K scattered (tf32-rounded) to [B,H,T,D]; V transposed to [B,H,D,T].
// Each warp's 64-wide N range = exactly one head.
// ---------------------------------------------------------------------------
#define GPAD 20
#define GA_U32 (128 * GPAD)               // A stage: 10240 B
#define GB_U32 (256 * GPAD)               // B stage: 20480 B
#define GSTAGE_U32 (GA_U32 + GB_U32)
#define GEMM_SMEM_BYTES (4 * GSTAGE_U32 * 4)   // 122880 B

__global__ __launch_bounds__(256) void qkv_gemm_tf32(
    const float* __restrict__ b)
{
    extern __shared__ uint32_t gsm[];
    // stage s: A at s*GSTAGE_U32, B at s*GSTAGE_U32 + GA_U32

    const int tid  = threadIdx.x;
    const int lane = tid & 31;
    const int warp = tid >> 5;
    const int wm = warp >> 2;              // 0..1 (64 rows each)
    const int wn = warp & 3;               // 0..3 (64 cols each)
    const int m0 = blockIdx.y * 128;
    const int n0 = blockIdx.x * 256;

    const uint32_t sBase = smem_u32(gsm);

    const uint32_t offA = ((((lane & 7) + ((lane >> 3) & 1) * 8) * GPAD)
                           + (lane >> 4) * 4) * 4;
    const uint32_t offBP = ((((lane & 7) + (lane >> 4) * 8) * GPAD)
                            + ((lane >> 3) & 1) * 4) * 4;

    // producers: A row tid>>1 (2 cp16); B rows tid>>1 and tid>>1+128 (4 cp16)
    const int lrow = tid >> 1;
    const int lcol = (tid & 1) * 8;
    const float* ap  = g_xt + (size_t)(m0 + lrow) * C_DIM + lcol;
    const float* bp0 = g_wt + (size_t)(n0 + lrow) * C_DIM + lcol;
    const float* bp1 = g_wt + (size_t)(n0 + lrow + 128) * C_DIM + lcol;
    const uint32_t aDst  = sBase + (lrow * GPAD + lcol) * 4;
    const uint32_t bDst0 = sBase + (GA_U32 + lrow * GPAD + lcol) * 4;
    const uint32_t bDst1 = sBase + (GA_U32 + (lrow + 128) * GPAD + lcol) * 4;

    float acc[4][8][4] = {};

    // prologue: stages 0..2 in flight
    #pragma unroll
    for (int s = 0; s < 3; s++) {
        const uint32_t so = (uint32_t)s * (GSTAGE_U32 * 4);
        cp16(aDst + so,       ap  + s * 16);
        cp16(aDst + so + 16,  ap  + s * 16 + 4);
        cp16(bDst0 + so,      bp0 + s * 16);
        cp16(bDst0 + so + 16, bp0 + s * 16 + 4);
        cp16(bDst1 + so,      bp1 + s * 16);
        cp16(bDst1 + so + 16, bp1 + s * 16 + 4);
        CP_COMMIT();
    }

    #pragma unroll 1
    for (int kt = 0; kt < 64; kt++) {
        CP_WAIT2();          // tile kt landed
        __syncthreads();     // visible to all; stage (kt+3)&3 readers done

        if (kt + 3 < 64) {
            const int kn = kt + 3;
            const uint32_t so = (uint32_t)(kn & 3) * (GSTAGE_U32 * 4);
            cp16(aDst + so,       ap  + kn * 16);
            cp16(aDst + so + 16,  ap  + kn * 16 + 4);
            cp16(bDst0 + so,      bp0 + kn * 16);
            cp16(bDst0 + so + 16, bp0 + kn * 16 + 4);
            cp16(bDst1 + so,      bp1 + kn * 16);
            cp16(bDst1 + so + 16, bp1 + kn * 16 + 4);
        }
        CP_COMMIT();

        const uint32_t aS = sBase + (uint32_t)(kt & 3) * (GSTAGE_U32 * 4);
        const uint32_t bS = aS + GA_U32 * 4;

        #pragma unroll
        for (int ks = 0; ks < 16; ks += 8) {
            uint32_t af[4][4];
            #pragma unroll
            for (int mt = 0; mt < 4; mt++) {
                ldsm4(af[mt][0], af[mt][1], af[mt][2], af[mt][3],
                      aS + ((wm * 64 + mt * 16) * GPAD + ks) * 4 + offA);
            }
            uint32_t bf[8][2];
            #pragma unroll
            for (int np = 0; np < 4; np++) {
                ldsm4(bf[2 * np][0], bf[2 * np][1],
                      bf[2 * np + 1][0], bf[2 * np + 1][1],
                      bS + ((wn * 64 + np * 16) * GPAD + ks) * 4 + offBP);
            }
            #pragma unroll
            for (int mt = 0; mt < 4; mt++)
                #pragma unroll
                for (int nt = 0; nt < 8; nt++)
                    mma_tf32(acc[mt][nt], af[mt], bf[nt][0], bf[nt][1]);
        }
    }

    // Epilogue: warp's absolute N base (nabs) lies in one head of one q/k/v third
    const int nabs  = n0 + wn * 64;
    const int which = nabs >> 10;
    const int bq = m0 >> 11;
    const int t0 = m0 & (T_DIM - 1);
    const int h  = (nabs & 1023) >> 6;

    if (which < 2) {
        float* dst = (which == 0) ? g_q : g_k;
        const size_t rowbase = (size_t)(bq * H_DIM + h) * T_DIM;
        #pragma unroll
        for (int nt = 0; nt < 8; nt++) {
            const int d = nt * 8 + 2 * (lane & 3);
            const float2 bias = *(const float2*)(b + nabs + d);
            #pragma unroll
            for (int mt = 0; mt < 4; mt++) {
                const int t = t0 + wm * 64 + mt * 16 + (lane >> 2);
                float2 v0 = { __uint_as_float(f2tf(acc[mt][nt][0] + bias.x)),
                              __uint_as_float(f2tf(acc[mt][nt][1] + bias.y)) };
                float2 v1 = { __uint_as_float(f2tf(acc[mt][nt][2] + bias.x)),
                              __uint_as_float(f2tf(acc[mt][nt][3] + bias.y)) };
                *(float2*)(dst + (rowbase + t) * HD + d)     = v0;
                *(float2*)(dst + (rowbase + t + 8) * HD + d) = v1;
            }
        }
    } else {
        // V: transposed scatter (tf32-rounded) to [B,H,D,T]
        const size_t hb = (size_t)(bq * H_DIM + h) * HD;
        #pragma unroll
        for (int nt = 0; nt < 8; nt++) {
            const int d = nt * 8 + 2 * (lane & 3);
            const float2 bias = *(const float2*)(b + nabs + d);
            float* r0 = g_v + (hb + d)     * T_DIM;
            float* r1 = g_v + (hb + d + 1) * T_DIM;
            #pragma unroll
            for (int mt = 0; mt < 4; mt++) {
                const int t = t0 + wm * 64 + mt * 16 + (lane >> 2);
                r0[t]     = __uint_as_float(f2tf(acc[mt][nt][0] + bias.x));
                r1[t]     = __uint_as_float(f2tf(acc[mt][nt][1] + bias.y));
                r0[t + 8] = __uint_as_float(f2tf(acc[mt][nt][2] + bias.x));
                r1[t + 8] = __uint_as_float(f2tf(acc[mt][nt][3] + bias.y));
            }
        }
    }
}

// ---------------------------------------------------------------------------
// Flash attention: 128 q-rows/CTA, 4 warps x 32 rows. KV tiles of 64,
// double-buffered via cp.async (1-tile lookahead), ONE sync per tile.
// (byte-identical to round 10 — known good)
// ---------------------------------------------------------------------------
#define APAD 68
#define KV_U32 (64 * APAD)
#define SMEM_U32 (4 * KV_U32 + 128 * APAD)   // Ks[2],Vt[2],Ps
#define ATTN_SMEM_BYTES (SMEM_U32 * 4)
#define SC 0.1803368801111204f   // (1/8) * log2(e)

__global__ __launch_bounds__(128, 2) void attn_tf32(float* __restrict__ out)
{
    extern __shared__ uint32_t sm[];
    const uint32_t ksBase = smem_u32(sm);
    const uint32_t vtBase = ksBase + 2 * KV_U32 * 4;
    const uint32_t psBase = ksBase + 4 * KV_U32 * 4;
    uint32_t (*Ps)[APAD] = (uint32_t(*)[APAD])(sm + 4 * KV_U32);

    const int tid  = threadIdx.x;
    const int lane = tid & 31;
    const int warp = tid >> 5;
    const int qt = (gridDim.x - 1) - blockIdx.x;   // heavy tiles first
    const int bh = blockIdx.y;

    const uint32_t offA = ((((lane & 7) + ((lane >> 3) & 1) * 8) * APAD)
                           + (lane >> 4) * 4) * 4;
    const uint32_t offB = (((lane & 7) * APAD) + (lane >> 3) * 4) * 4;

    const float* Qg  = g_q + (size_t)bh * T_DIM * HD;
    const float* Kg  = g_k + (size_t)bh * T_DIM * HD;
    const float* Vgt = g_v + (size_t)bh * HD * T_DIM;

    const int srow = tid >> 1;           // 0..63
    const int ch   = (tid & 1) * 32;     // 0 or 32
    const uint32_t kDst = ksBase + (srow * APAD + ch) * 4;
    const uint32_t vDst = vtBase + (srow * APAD + ch) * 4;

    // ---- stage Q raw (pre-rounded), pull qa fragments ----
    {
        const uint4* qp = (const uint4*)(Qg + (size_t)(qt * 128 + tid) * HD);
        #pragma unroll
        for (int i = 0; i < 16; i++) *(uint4*)&Ps[tid][i * 4] = qp[i];
    }
    // ---- prologue: KV tile 0 in flight ----
    {
        const float* kp = Kg  + (size_t)srow * HD + ch;
        const float* vp = Vgt + (size_t)srow * T_DIM + ch;
        #pragma unroll
        for (int i = 0; i < 8; i++) {
            cp16(kDst + i * 16, kp + i * 4);
            cp16(vDst + i * 16, vp + i * 4);
        }
        CP_COMMIT();
    }
    __syncwarp();
    uint32_t qa[2][8][4];
    #pragma unroll
    for (int mt = 0; mt < 2; mt++)
        #pragma unroll
        for (int k = 0; k < 8; k++)
            ldsm4(qa[mt][k][0], qa[mt][k][1], qa[mt][k][2], qa[mt][k][3],
                  psBase + ((warp * 32 + mt * 16) * APAD + k * 8) * 4 + offA);

    float oa[2][8][4] = {};
    float mr[2][2] = {{-1e30f, -1e30f}, {-1e30f, -1e30f}};
    float lv[2][2] = {};
    const int rbase = qt * 128 + warp * 32;
    const int NKV = 2 * qt + 2;

    for (int kt = 0; kt < NKV; kt++) {
        CP_WAIT0();
        __syncthreads();

        if (kt + 1 < NKV) {
            const int kn = kt + 1;
            const uint32_t bo = (uint32_t)(kn & 1) * (KV_U32 * 4);
            const float* kp = Kg  + (size_t)(kn * 64 + srow) * HD + ch;
            const float* vp = Vgt + (size_t)srow * T_DIM + kn * 64 + ch;
            #pragma unroll
            for (int i = 0; i < 8; i++) {
                cp16(kDst + bo + i * 16, kp + i * 4);
                cp16(vDst + bo + i * 16, vp + i * 4);
            }
        }
        CP_COMMIT();

        if (kt * 64 > rbase + 31) continue;

        const uint32_t bo = (uint32_t)(kt & 1) * (KV_U32 * 4);

        // ---- S = Q @ K^T ----
        float s[2][8][4] = {};
        #pragma unroll
        for (int kp2 = 0; kp2 < 4; kp2++) {
            #pragma unroll
            for (int j = 0; j < 8; j++) {
                uint32_t b0, b1, b2, b3;
                ldsm4(b0, b1, b2, b3,
                      ksBase + bo + ((j * 8) * APAD + kp2 * 16) * 4 + offB);
                mma_tf32(s[0][j], qa[0][2 * kp2],     b0, b1);
                mma_tf32(s[0][j], qa[0][2 * kp2 + 1], b2, b3);
                mma_tf32(s[1][j], qa[1][2 * kp2],     b0, b1);
                mma_tf32(s[1][j], qa[1][2 * kp2 + 1], b2, b3);
            }
        }

        if (kt * 64 + 63 > rbase) {
            #pragma unroll
            for (int mt = 0; mt < 2; mt++) {
                const int gr0 = rbase + mt * 16 + (lane >> 2);
                const int gr1 = gr0 + 8;
                #pragma unroll
                for (int j = 0; j < 8; j++) {
                    const int c0 = kt * 64 + j * 8 + 2 * (lane & 3);
                    if (c0     > gr0) s[mt][j][0] = -1e30f;
                    if (c0 + 1 > gr0) s[mt][j][1] = -1e30f;
                    if (c0     > gr1) s[mt][j][2] = -1e30f;
                    if (c0 + 1 > gr1) s[mt][j][3] = -1e30f;
                }
            }
        }

        #pragma unroll
        for (int mt = 0; mt < 2; mt++) {
            float mx0 = -1e30f, mx1 = -1e30f;
            #pragma unroll
            for (int j = 0; j < 8; j++) {
                mx0 = fmaxf(mx0, fmaxf(s[mt][j][0], s[mt][j][1]));
                mx1 = fmaxf(mx1, fmaxf(s[mt][j][2], s[mt][j][3]));
            }
            mx0 = fmaxf(mx0, __shfl_xor_sync(0xffffffff, mx0, 1));
            mx0 = fmaxf(mx0, __shfl_xor_sync(0xffffffff, mx0, 2));
            mx1 = fmaxf(mx1, __shfl_xor_sync(0xffffffff, mx1, 1));
            mx1 = fmaxf(mx1, __shfl_xor_sync(0xffffffff, mx1, 2));

            const float nm0 = fmaxf(mr[mt][0], mx0);
            const float nm1 = fmaxf(mr[mt][1], mx1);
            const float nm0c = nm0 * SC;
            const float nm1c = nm1 * SC;
            const float corr0 = ex2(fmaf(mr[mt][0], SC, -nm0c));
            const float corr1 = ex2(fmaf(mr[mt][1], SC, -nm1c));
            mr[mt][0] = nm0; mr[mt][1] = nm1;

            float sum0 = 0.0f, sum1 = 0.0f;
            #pragma unroll
            for (int j = 0; j < 8; j++) {
                s[mt][j][0] = ex2(fmaf(s[mt][j][0], SC, -nm0c)); sum0 += s[mt][j][0];
                s[mt][j][1] = ex2(fmaf(s[mt][j][1], SC, -nm0c)); sum0 += s[mt][j][1];
                s[mt][j][2] = ex2(fmaf(s[mt][j][2], SC, -nm1c)); sum1 += s[mt][j][2];
                s[mt][j][3] = ex2(fmaf(s[mt][j][3], SC, -nm1c)); sum1 += s[mt][j][3];
            }
            sum0 += __shfl_xor_sync(0xffffffff, sum0, 1);
            sum0 += __shfl_xor_sync(0xffffffff, sum0, 2);
            sum1 += __shfl_xor_sync(0xffffffff, sum1, 1);
            sum1 += __shfl_xor_sync(0xffffffff, sum1, 2);
            lv[mt][0] = lv[mt][0] * corr0 + sum0;
            lv[mt][1] = lv[mt][1] * corr1 + sum1;

            #pragma unroll
            for (int j = 0; j < 8; j++) {
                oa[mt][j][0] *= corr0; oa[mt][j][1] *= corr0;
                oa[mt][j][2] *= corr1; oa[mt][j][3] *= corr1;
            }

            const int r = warp * 32 + mt * 16 + (lane >> 2);
            #pragma unroll
            for (int j = 0; j < 8; j++) {
                const int c = j * 8 + 2 * (lane & 3);
                uint2 u0 = { f2tf(s[mt][j][0]), f2tf(s[mt][j][1]) };
                uint2 u1 = { f2tf(s[mt][j][2]), f2tf(s[mt][j][3]) };
                *(uint2*)&Ps[r][c]     = u0;
                *(uint2*)&Ps[r + 8][c] = u1;
            }
        }
        __syncwarp();

        // ---- O += P @ V ----
        #pragma unroll
        for (int kp2 = 0; kp2 < 4; kp2++) {
            uint32_t a0[4], a1[4], a2[4], a3[4];
            ldsm4(a0[0], a0[1], a0[2], a0[3],
                  psBase + ((warp * 32) * APAD + kp2 * 16) * 4 + offA);
            ldsm4(a1[0], a1[1], a1[2], a1[3],
                  psBase + ((warp * 32) * APAD + kp2 * 16 + 8) * 4 + offA);
            ldsm4(a2[0], a2[1], a2[2], a2[3],
                  psBase + ((warp * 32 + 16) * APAD + kp2 * 16) * 4 + offA);
            ldsm4(a3[0], a3[1], a3[2], a3[3],
                  psBase + ((warp * 32 + 16) * APAD + kp2 * 16 + 8) * 4 + offA);
            #pragma unroll
            for (int j = 0; j < 8; j++) {
                uint32_t b0, b1, b2, b3;
                ldsm4(b0, b1, b2, b3,
                      vtBase + bo + ((j * 8) * APAD + kp2 * 16) * 4 + offB);
                mma_tf32(oa[0][j], a0, b0, b1);
                mma_tf32(oa[0][j], a1, b2, b3);
                mma_tf32(oa[1][j], a2, b0, b1);
                mma_tf32(oa[1][j], a3, b2, b3);
            }
        }
    }

    // ---- epilogue ----
    const int bq = bh >> 4;
    const int h  = bh & 15;
    #pragma unroll
    for (int mt = 0; mt < 2; mt++) {
        const float inv0 = 1.0f / lv[mt][0];
        const float inv1 = 1.0f / lv[mt][1];
        const int trow = rbase + mt * 16 + (lane >> 2);
        #pragma unroll
        for (int j = 0; j < 8; j++) {
            const int d = j * 8 + 2 * (lane & 3);
            float2 v0 = { oa[mt][j][0] * inv0, oa[mt][j][1] * inv0 };
            float2 v1 = { oa[mt][j][2] * inv1, oa[mt][j][3] * inv1 };
            *(float2*)(out + (size_t)(bq * T_DIM + trow) * C_DIM + h * HD + d)     = v0;
            *(float2*)(out + (size_t)(bq * T_DIM + trow + 8) * C_DIM + h * HD + d) = v1;
        }
    }
}

// ---------------------------------------------------------------------------
extern "C" void kernel_launch(void* const* d_in, const int* in_sizes, int n_in,
                              void* d_out, int out_size)
{
    const float* x = (const float*)d_in[0];   // [4, 2048, 1024]
    const float* W = (const float*)d_in[1];   // [3072, 1024]
    const float* b = (const float*)d_in[2];   // [3072]
    float* out = (float*)d_out;               // [4, 2048, 1024]

    cudaFuncSetAttribute(qkv_gemm_tf32, cudaFuncAttributeMaxDynamicSharedMemorySize,
                         GEMM_SMEM_BYTES);
    cudaFuncSetAttribute(attn_tf32, cudaFuncAttributeMaxDynamicSharedMemorySize,
                         ATTN_SMEM_BYTES);

    const size_t ncvt = ((size_t)M_TOT * C_DIM + (size_t)N_TOT * C_DIM) / 4;
    cvt_pre<<<(unsigned)((ncvt + 255) / 256), 256>>>(x, W);
    qkv_gemm_tf32<<<dim3(N_TOT / 256, M_TOT / 128), 256, GEMM_SMEM_BYTES>>>(b);
    attn_tf32<<<dim3(T_DIM / 128, B_DIM * H_DIM), 128, ATTN_SMEM_BYTES>>>(out);
}

// round 12
// speedup vs baseline: 1.0998x; 1.0998x over previous
#include <cuda_runtime.h>
#include <cstdint>

#define C_DIM 1024
#define B_DIM 4
#define T_DIM 2048
#define H_DIM 16
#define HD    64
#define M_TOT (B_DIM * T_DIM)   // 8192
#define N_TOT (3 * C_DIM)       // 3072

// Q/K in [B,H,T,D]; V TRANSPOSED in [B,H,D,T] with time-index permuted
// within each 8-block (PV-mma layout). All tf32-rounded fp32 bits.
__device__ float g_q[(size_t)M_TOT * C_DIM];
__device__ float g_k[(size_t)M_TOT * C_DIM];
__device__ float g_v[(size_t)M_TOT * C_DIM];
// tf32-rounded copies of inputs
__device__ float g_xt[(size_t)M_TOT * C_DIM];
__device__ float g_wt[(size_t)N_TOT * C_DIM];

__device__ __forceinline__ uint32_t f2tf(float f) {
    uint32_t u;
    asm("cvt.rna.tf32.f32 %0, %1;" : "=r"(u) : "f"(f));
    return u;
}

__device__ __forceinline__ float ex2(float x) {
    float y;
    asm("ex2.approx.f32 %0, %1;" : "=f"(y) : "f"(x));
    return y;
}

__device__ __forceinline__ void mma_tf32(float c[4], const uint32_t a[4],
                                         uint32_t b0, uint32_t b1) {
    asm volatile(
        "mma.sync.aligned.m16n8k8.row.col.f32.tf32.tf32.f32 "
        "{%0,%1,%2,%3}, {%4,%5,%6,%7}, {%8,%9}, {%0,%1,%2,%3};"
        : "+f"(c[0]), "+f"(c[1]), "+f"(c[2]), "+f"(c[3])
        : "r"(a[0]), "r"(a[1]), "r"(a[2]), "r"(a[3]), "r"(b0), "r"(b1));
}

__device__ __forceinline__ void ldsm4(uint32_t& d0, uint32_t& d1,
                                      uint32_t& d2, uint32_t& d3,
                                      uint32_t addr) {
    asm volatile("ldmatrix.sync.aligned.m8n8.x4.shared.b16 {%0,%1,%2,%3}, [%4];"
                 : "=r"(d0), "=r"(d1), "=r"(d2), "=r"(d3) : "r"(addr));
}

__device__ __forceinline__ uint32_t smem_u32(const void* p) {
    uint32_t a;
    asm("{ .reg .u64 t; cvta.to.shared.u64 t, %1; cvt.u32.u64 %0, t; }"
        : "=r"(a) : "l"(p));
    return a;
}

__device__ __forceinline__ void cp16(uint32_t dst, const void* src) {
    asm volatile("cp.async.cg.shared.global [%0], [%1], 16;"
                 :: "r"(dst), "l"(src));
}
#define CP_COMMIT() asm volatile("cp.async.commit_group;" ::: "memory")
#define CP_WAIT0()  asm volatile("cp.async.wait_group 0;" ::: "memory")
#define CP_WAIT2()  asm volatile("cp.async.wait_group 2;" ::: "memory")

// ---------------------------------------------------------------------------
// Prepass: tf32-round (rna) x and W into scratch copies.
// ---------------------------------------------------------------------------
__global__ __launch_bounds__(256) void cvt_pre(
    const float* __restrict__ x, const float* __restrict__ W)
{
    const size_t nx = (size_t)M_TOT * C_DIM / 4;
    const size_t nw = (size_t)N_TOT * C_DIM / 4;
    size_t i = (size_t)blockIdx.x * blockDim.x + threadIdx.x;
    if (i < nx) {
        float4 v = ((const float4*)x)[i];
        uint4 u = { f2tf(v.x), f2tf(v.y), f2tf(v.z), f2tf(v.w) };
        ((uint4*)g_xt)[i] = u;
    } else if (i < nx + nw) {
        float4 v = ((const float4*)W)[i - nx];
        uint4 u = { f2tf(v.x), f2tf(v.y), f2tf(v.z), f2tf(v.w) };
        ((uint4*)g_wt)[i - nx] = u;
    }
}

// ---------------------------------------------------------------------------
// QKV GEMM: round-10 config (proven): CTA 128x128, k16, 8 warps (2Mx4N),
// 4-stage cp.async ring, ONE sync per k-tile, ldmatrix fragments.
// Q/K scattered (tf32-rounded) to [B,H,T,D]; V transposed to [B,H,D,T]
// with time index PERMUTED within each 8-block: t' = ((t&1)<<2)|((t&7)>>1).
// ---------------------------------------------------------------------------
#define GPAD 20
#define GSTAGE_U32 (128 * GPAD)
#define GEMM_SMEM_BYTES (8 * GSTAGE_U32 * 4)   // (A+B) x 4 stages = 81920 B

__global__ __launch_bounds__(256, 2) void qkv_gemm_tf32(
    const float* __restrict__ b)
{
    extern __shared__ uint32_t gsm[];
    uint32_t* Abuf = gsm;                     // [4][128][GPAD]
    uint32_t* Bbuf = gsm + 4 * GSTAGE_U32;    // [4][128][GPAD]

    const int tid  = threadIdx.x;
    const int lane = tid & 31;
    const int warp = tid >> 5;
    const int wm = warp >> 2;
    const int wn = warp & 3;
    const int m0 = blockIdx.y * 128;
    const int n0 = blockIdx.x * 128;

    const uint32_t aBase = smem_u32(Abuf);
    const uint32_t bBase = smem_u32(Bbuf);

    const uint32_t offA = ((((lane & 7) + ((lane >> 3) & 1) * 8) * GPAD)
                           + (lane >> 4) * 4) * 4;
    const uint32_t offBP = ((((lane & 7) + (lane >> 4) * 8) * GPAD)
                            + ((lane >> 3) & 1) * 4) * 4;

    const int lrow = tid >> 1;
    const int lcol = (tid & 1) * 8;
    const float* ap = g_xt + (size_t)(m0 + lrow) * C_DIM + lcol;
    const float* bp = g_wt + (size_t)(n0 + lrow) * C_DIM + lcol;
    const uint32_t aDst = aBase + (lrow * GPAD + lcol) * 4;
    const uint32_t bDst = bBase + (lrow * GPAD + lcol) * 4;

    float acc[4][4][4] = {};

    #pragma unroll
    for (int s = 0; s < 3; s++) {
        const uint32_t so = (uint32_t)s * (GSTAGE_U32 * 4);
        cp16(aDst + so, ap + s * 16);
        cp16(aDst + so + 16, ap + s * 16 + 4);
        cp16(bDst + so, bp + s * 16);
        cp16(bDst + so + 16, bp + s * 16 + 4);
        CP_COMMIT();
    }

    #pragma unroll 1
    for (int kt = 0; kt < 64; kt++) {
        CP_WAIT2();
        __syncthreads();

        if (kt + 3 < 64) {
            const int kn = kt + 3;
            const uint32_t so = (uint32_t)(kn & 3) * (GSTAGE_U32 * 4);
            cp16(aDst + so, ap + kn * 16);
            cp16(aDst + so + 16, ap + kn * 16 + 4);
            cp16(bDst + so, bp + kn * 16);
            cp16(bDst + so + 16, bp + kn * 16 + 4);
        }
        CP_COMMIT();

        const uint32_t soff = (uint32_t)(kt & 3) * (GSTAGE_U32 * 4);
        #pragma unroll
        for (int ks = 0; ks < 16; ks += 8) {
            uint32_t af[4][4];
            #pragma unroll
            for (int mt = 0; mt < 4; mt++) {
                ldsm4(af[mt][0], af[mt][1], af[mt][2], af[mt][3],
                      aBase + soff + ((wm * 64 + mt * 16) * GPAD + ks) * 4 + offA);
            }
            uint32_t bf[4][2];
            ldsm4(bf[0][0], bf[0][1], bf[1][0], bf[1][1],
                  bBase + soff + ((wn * 32) * GPAD + ks) * 4 + offBP);
            ldsm4(bf[2][0], bf[2][1], bf[3][0], bf[3][1],
                  bBase + soff + ((wn * 32 + 16) * GPAD + ks) * 4 + offBP);
            #pragma unroll
            for (int mt = 0; mt < 4; mt++)
                #pragma unroll
                for (int nt = 0; nt < 4; nt++)
                    mma_tf32(acc[mt][nt], af[mt], bf[nt][0], bf[nt][1]);
        }
    }

    const int which = n0 >> 10;
    const int bq = m0 >> 11;
    const int t0 = m0 & (T_DIM - 1);
    const int h  = (((n0 & 1023) + wn * 32) >> 6);

    if (which < 2) {
        float* dst = (which == 0) ? g_q : g_k;
        #pragma unroll
        for (int nt = 0; nt < 4; nt++) {
            const int ncol = wn * 32 + nt * 8 + 2 * (lane & 3);
            const float2 bias = *(const float2*)(b + n0 + ncol);
            const int d = ncol & 63;
            const size_t rowbase = (size_t)(bq * H_DIM + h) * T_DIM;
            #pragma unroll
            for (int mt = 0; mt < 4; mt++) {
                const int t = t0 + wm * 64 + mt * 16 + (lane >> 2);
                float2 v0 = { __uint_as_float(f2tf(acc[mt][nt][0] + bias.x)),
                              __uint_as_float(f2tf(acc[mt][nt][1] + bias.y)) };
                float2 v1 = { __uint_as_float(f2tf(acc[mt][nt][2] + bias.x)),
                              __uint_as_float(f2tf(acc[mt][nt][3] + bias.y)) };
                *(float2*)(dst + (rowbase + t) * HD + d)     = v0;
                *(float2*)(dst + (rowbase + t + 8) * HD + d) = v1;
            }
        }
    } else {
        // V: transposed scatter to [B,H,D,T], time permuted within 8-blocks
        const size_t hb = (size_t)(bq * H_DIM + h) * HD;
        const int u  = lane >> 2;                      // 0..7
        const int up = ((u & 1) << 2) | (u >> 1);      // PV-mma k permutation
        #pragma unroll
        for (int nt = 0; nt < 4; nt++) {
            const int ncol = wn * 32 + nt * 8 + 2 * (lane & 3);
            const float2 bias = *(const float2*)(b + n0 + ncol);
            const int d = ncol & 63;
            float* r0 = g_v + (hb + d)     * T_DIM;
            float* r1 = g_v + (hb + d + 1) * T_DIM;
            #pragma unroll
            for (int mt = 0; mt < 4; mt++) {
                const int t = t0 + wm * 64 + mt * 16 + up;
                r0[t]     = __uint_as_float(f2tf(acc[mt][nt][0] + bias.x));
                r1[t]     = __uint_as_float(f2tf(acc[mt][nt][1] + bias.y));
                r0[t + 8] = __uint_as_float(f2tf(acc[mt][nt][2] + bias.x));
                r1[t + 8] = __uint_as_float(f2tf(acc[mt][nt][3] + bias.y));
            }
        }
    }
}

// ---------------------------------------------------------------------------
// Flash attention: 128 q-rows/CTA, 4 warps x 32 rows. KV tiles of 64,
// double-buffered via cp.async. P feeds PV mma DIRECTLY from softmax
// registers (A = {s0,s2,s1,s3}); V is pre-permuted to match. No Ps buffer:
// smem = Ks[2] + Vt[2] only (Q staged through the Vt region pre-pipeline).
// ---------------------------------------------------------------------------
#define APAD 68
#define KV_U32 (64 * APAD)
#define SMEM_U32 (4 * KV_U32)          // Ks[2], Vt[2]
#define ATTN_SMEM_BYTES (SMEM_U32 * 4) // 69632 B
#define SC 0.1803368801111204f   // (1/8) * log2(e)

__global__ __launch_bounds__(128, 2) void attn_tf32(float* __restrict__ out)
{
    extern __shared__ uint32_t sm[];
    const uint32_t ksBase = smem_u32(sm);
    const uint32_t vtBase = ksBase + 2 * KV_U32 * 4;

    const int tid  = threadIdx.x;
    const int lane = tid & 31;
    const int warp = tid >> 5;
    const int qt = (gridDim.x - 1) - blockIdx.x;   // heavy tiles first
    const int bh = blockIdx.y;

    const uint32_t offA = ((((lane & 7) + ((lane >> 3) & 1) * 8) * APAD)
                           + (lane >> 4) * 4) * 4;
    const uint32_t offB = (((lane & 7) * APAD) + (lane >> 3) * 4) * 4;

    const float* Qg  = g_q + (size_t)bh * T_DIM * HD;
    const float* Kg  = g_k + (size_t)bh * T_DIM * HD;
    const float* Vgt = g_v + (size_t)bh * HD * T_DIM;

    const int srow = tid >> 1;           // 0..63
    const int ch   = (tid & 1) * 32;     // 0 or 32
    const uint32_t kDst = ksBase + (srow * APAD + ch) * 4;
    const uint32_t vDst = vtBase + (srow * APAD + ch) * 4;

    // ---- stage Q (raw, pre-rounded) through the Vt[2] region, pull qa ----
    {
        const uint4* qp = (const uint4*)(Qg + (size_t)(qt * 128 + tid) * HD);
        uint32_t qrow = vtBase + (tid * APAD) * 4;
        #pragma unroll
        for (int i = 0; i < 16; i++) {
            uint4 v = qp[i];
            asm volatile("st.shared.v4.b32 [%0], {%1,%2,%3,%4};"
                         :: "r"(qrow + i * 16), "r"(v.x), "r"(v.y),
                            "r"(v.z), "r"(v.w) : "memory");
        }
    }
    __syncthreads();
    uint32_t qa[2][8][4];
    #pragma unroll
    for (int mt = 0; mt < 2; mt++)
        #pragma unroll
        for (int k = 0; k < 8; k++)
            ldsm4(qa[mt][k][0], qa[mt][k][1], qa[mt][k][2], qa[mt][k][3],
                  vtBase + ((warp * 32 + mt * 16) * APAD + k * 8) * 4 + offA);
    __syncthreads();   // all qa reads done before Vt is reused for V

    // ---- prologue: KV tile 0 in flight ----
    {
        const float* kp = Kg  + (size_t)srow * HD + ch;
        const float* vp = Vgt + (size_t)srow * T_DIM + ch;
        #pragma unroll
        for (int i = 0; i < 8; i++) {
            cp16(kDst + i * 16, kp + i * 4);
            cp16(vDst + i * 16, vp + i * 4);
        }
        CP_COMMIT();
    }

    float oa[2][8][4] = {};
    float mr[2][2] = {{-1e30f, -1e30f}, {-1e30f, -1e30f}};
    float lv[2][2] = {};
    const int rbase = qt * 128 + warp * 32;
    const int NKV = 2 * qt + 2;

    for (int kt = 0; kt < NKV; kt++) {
        CP_WAIT0();
        __syncthreads();

        if (kt + 1 < NKV) {
            const int kn = kt + 1;
            const uint32_t bo = (uint32_t)(kn & 1) * (KV_U32 * 4);
            const float* kp = Kg  + (size_t)(kn * 64 + srow) * HD + ch;
            const float* vp = Vgt + (size_t)srow * T_DIM + kn * 64 + ch;
            #pragma unroll
            for (int i = 0; i < 8; i++) {
                cp16(kDst + bo + i * 16, kp + i * 4);
                cp16(vDst + bo + i * 16, vp + i * 4);
            }
        }
        CP_COMMIT();

        if (kt * 64 > rbase + 31) continue;

        const uint32_t bo = (uint32_t)(kt & 1) * (KV_U32 * 4);

        // ---- S = Q @ K^T ----
        float s[2][8][4] = {};
        #pragma unroll
        for (int kp2 = 0; kp2 < 4; kp2++) {
            #pragma unroll
            for (int j = 0; j < 8; j++) {
                uint32_t b0, b1, b2, b3;
                ldsm4(b0, b1, b2, b3,
                      ksBase + bo + ((j * 8) * APAD + kp2 * 16) * 4 + offB);
                mma_tf32(s[0][j], qa[0][2 * kp2],     b0, b1);
                mma_tf32(s[0][j], qa[0][2 * kp2 + 1], b2, b3);
                mma_tf32(s[1][j], qa[1][2 * kp2],     b0, b1);
                mma_tf32(s[1][j], qa[1][2 * kp2 + 1], b2, b3);
            }
        }

        // ---- causal mask (diagonal-overlapping tiles) ----
        if (kt * 64 + 63 > rbase) {
            #pragma unroll
            for (int mt = 0; mt < 2; mt++) {
                const int gr0 = rbase + mt * 16 + (lane >> 2);
                const int gr1 = gr0 + 8;
                #pragma unroll
                for (int j = 0; j < 8; j++) {
                    const int c0 = kt * 64 + j * 8 + 2 * (lane & 3);
                    if (c0     > gr0) s[mt][j][0] = -1e30f;
                    if (c0 + 1 > gr0) s[mt][j][1] = -1e30f;
                    if (c0     > gr1) s[mt][j][2] = -1e30f;
                    if (c0 + 1 > gr1) s[mt][j][3] = -1e30f;
                }
            }
        }

        // ---- online softmax (base-2, scale folded into ex2) ----
        #pragma unroll
        for (int mt = 0; mt < 2; mt++) {
            float mx0 = -1e30f, mx1 = -1e30f;
            #pragma unroll
            for (int j = 0; j < 8; j++) {
                mx0 = fmaxf(mx0, fmaxf(s[mt][j][0], s[mt][j][1]));
                mx1 = fmaxf(mx1, fmaxf(s[mt][j][2], s[mt][j][3]));
            }
            mx0 = fmaxf(mx0, __shfl_xor_sync(0xffffffff, mx0, 1));
            mx0 = fmaxf(mx0, __shfl_xor_sync(0xffffffff, mx0, 2));
            mx1 = fmaxf(mx1, __shfl_xor_sync(0xffffffff, mx1, 1));
            mx1 = fmaxf(mx1, __shfl_xor_sync(0xffffffff, mx1, 2));

            const float nm0 = fmaxf(mr[mt][0], mx0);
            const float nm1 = fmaxf(mr[mt][1], mx1);
            const float nm0c = nm0 * SC;
            const float nm1c = nm1 * SC;
            const float corr0 = ex2(fmaf(mr[mt][0], SC, -nm0c));
            const float corr1 = ex2(fmaf(mr[mt][1], SC, -nm1c));
            mr[mt][0] = nm0; mr[mt][1] = nm1;

            float sum0 = 0.0f, sum1 = 0.0f;
            #pragma unroll
            for (int j = 0; j < 8; j++) {
                s[mt][j][0] = ex2(fmaf(s[mt][j][0], SC, -nm0c)); sum0 += s[mt][j][0];
                s[mt][j][1] = ex2(fmaf(s[mt][j][1], SC, -nm0c)); sum0 += s[mt][j][1];
                s[mt][j][2] = ex2(fmaf(s[mt][j][2], SC, -nm1c)); sum1 += s[mt][j][2];
                s[mt][j][3] = ex2(fmaf(s[mt][j][3], SC, -nm1c)); sum1 += s[mt][j][3];
            }
            sum0 += __shfl_xor_sync(0xffffffff, sum0, 1);
            sum0 += __shfl_xor_sync(0xffffffff, sum0, 2);
            sum1 += __shfl_xor_sync(0xffffffff, sum1, 1);
            sum1 += __shfl_xor_sync(0xffffffff, sum1, 2);
            lv[mt][0] = lv[mt][0] * corr0 + sum0;
            lv[mt][1] = lv[mt][1] * corr1 + sum1;

            #pragma unroll
            for (int j = 0; j < 8; j++) {
                oa[mt][j][0] *= corr0; oa[mt][j][1] *= corr0;
                oa[mt][j][2] *= corr1; oa[mt][j][3] *= corr1;
            }
        }

        // ---- O += P @ V : A-frags straight from softmax registers ----
        // A-frag for k8 block κ = {s[κ][0], s[κ][2], s[κ][1], s[κ][3]}
        // (column permutation absorbed into V's pre-permuted storage)
        #pragma unroll
        for (int kp2 = 0; kp2 < 4; kp2++) {
            uint32_t A0[2][4], A1[2][4];
            #pragma unroll
            for (int mt = 0; mt < 2; mt++) {
                A0[mt][0] = f2tf(s[mt][2 * kp2][0]);
                A0[mt][1] = f2tf(s[mt][2 * kp2][2]);
                A0[mt][2] = f2tf(s[mt][2 * kp2][1]);
                A0[mt][3] = f2tf(s[mt][2 * kp2][3]);
                A1[mt][0] = f2tf(s[mt][2 * kp2 + 1][0]);
                A1[mt][1] = f2tf(s[mt][2 * kp2 + 1][2]);
                A1[mt][2] = f2tf(s[mt][2 * kp2 + 1][1]);
                A1[mt][3] = f2tf(s[mt][2 * kp2 + 1][3]);
            }
            #pragma unroll
            for (int j = 0; j < 8; j++) {
                uint32_t b0, b1, b2, b3;
                ldsm4(b0, b1, b2, b3,
                      vtBase + bo + ((j * 8) * APAD + kp2 * 16) * 4 + offB);
                mma_tf32(oa[0][j], A0[0], b0, b1);
                mma_tf32(oa[0][j], A1[0], b2, b3);
                mma_tf32(oa[1][j], A0[1], b0, b1);
                mma_tf32(oa[1][j], A1[1], b2, b3);
            }
        }
    }

    // ---- epilogue: normalize, write [B,T,C] ----
    const int bq = bh >> 4;
    const int h  = bh & 15;
    #pragma unroll
    for (int mt = 0; mt < 2; mt++) {
        const float inv0 = 1.0f / lv[mt][0];
        const float inv1 = 1.0f / lv[mt][1];
        const int trow = rbase + mt * 16 + (lane >> 2);
        #pragma unroll
        for (int j = 0; j < 8; j++) {
            const int d = j * 8 + 2 * (lane & 3);
            float2 v0 = { oa[mt][j][0] * inv0, oa[mt][j][1] * inv0 };
            float2 v1 = { oa[mt][j][2] * inv1, oa[mt][j][3] * inv1 };
            *(float2*)(out + (size_t)(bq * T_DIM + trow) * C_DIM + h * HD + d)     = v0;
            *(float2*)(out + (size_t)(bq * T_DIM + trow + 8) * C_DIM + h * HD + d) = v1;
        }
    }
}

// ---------------------------------------------------------------------------
extern "C" void kernel_launch(void* const* d_in, const int* in_sizes, int n_in,
                              void* d_out, int out_size)
{
    const float* x = (const float*)d_in[0];   // [4, 2048, 1024]
    const float* W = (const float*)d_in[1];   // [3072, 1024]
    const float* b = (const float*)d_in[2];   // [3072]
    float* out = (float*)d_out;               // [4, 2048, 1024]

    cudaFuncSetAttribute(qkv_gemm_tf32, cudaFuncAttributeMaxDynamicSharedMemorySize,
                         GEMM_SMEM_BYTES);
    cudaFuncSetAttribute(attn_tf32, cudaFuncAttributeMaxDynamicSharedMemorySize,
                         ATTN_SMEM_BYTES);

    const size_t ncvt = ((size_t)M_TOT * C_DIM + (size_t)N_TOT * C_DIM) / 4;
    cvt_pre<<<(unsigned)((ncvt + 255) / 256), 256>>>(x, W);
    qkv_gemm_tf32<<<dim3(N_TOT / 128, M_TOT / 128), 256, GEMM_SMEM_BYTES>>>(b);
    attn_tf32<<<dim3(T_DIM / 128, B_DIM * H_DIM), 128, ATTN_SMEM_BYTES>>>(out);
}